// round 3
// baseline (speedup 1.0000x reference)
#include <cuda_runtime.h>
#include <math.h>
#include <stdint.h>

// LSTM B=64, T=512, E=512, H=1024, D=1536, 10 classes.
//
// pack:    reorder weights into FMA2-friendly [k][gatecol] tiles; zero h0/flags.
// phase 1: pre[t][b][gc] = x_t @ Wx^T + bias   (8192 CTAs, parallel over t)
// phase 2: persistent 128-CTA kernel (16 jtiles x 8 K-slices), 512 steps,
//          weights resident in smem, c-state in registers of owner CTAs,
//          flag-based grid barrier, per-jtile partial-reduction flags.
// phase 3: FC to [64,10].
//
// Inner loops: packed fp32x2 FMA (FFMA2), 8x8 register tile per thread
// -> 1 byte smem traffic per MAC (smem at ~62% of the FMA2 window).

#define BB   64
#define TT   512
#define EE   512
#define HH   1024
#define DD   1536
#define NCLS 10
#define GC   4096          // gate-cols = 4*H
#define NJT  16            // j-tiles (256 gate-cols each)
#define NKT  8             // K-slices of the recurrent GEMM (128 k each)
#define KSL  128           // k per slice
#define NBLK (NJT * NKT)   // 128 persistent CTAs
#define NTHREADS 256
#define SMEM_BYTES 163840  // 40960 floats: 32768 (W tile) + 8192 (H/A tile)

static __device__ float g_pre[(size_t)TT * BB * GC];          // 512 MB
static __device__ float g_Wxp[(size_t)NJT * EE * 256];        // [jt][k][c]
static __device__ float g_Whp[(size_t)NKT * NJT * KSL * 256]; // [kt][jt][k][c]
static __device__ float g_biasp[GC];
static __device__ float g_part[(size_t)NKT * BB * GC];        // partial sums
static __device__ float g_h[2][BB * HH];
static __device__ unsigned g_flags[NBLK];                     // barrier arrive
static __device__ unsigned g_jflags[NJT][NKT];                // partial ready
static __device__ unsigned g_rel;                             // barrier release

typedef unsigned long long ull;

// ------------------------------------------------------------- f32x2 helpers
__device__ __forceinline__ ull pack2(float x, float y) {
    ull r; asm("mov.b64 %0, {%1, %2};" : "=l"(r) : "f"(x), "f"(y)); return r;
}
__device__ __forceinline__ void fma2(ull& d, ull a, ull b) {
    asm("fma.rn.f32x2 %0, %1, %2, %3;" : "=l"(d) : "l"(a), "l"(b), "l"(d));
}
__device__ __forceinline__ void add2(ull& d, ull a) {
    asm("add.rn.f32x2 %0, %1, %2;" : "=l"(d) : "l"(d), "l"(a));
}
__device__ __forceinline__ float2 unpack2(ull v) {
    float2 f; asm("mov.b64 {%0, %1}, %2;" : "=f"(f.x), "=f"(f.y) : "l"(v)); return f;
}
__device__ __forceinline__ float sigf(float x) { return 1.0f / (1.0f + expf(-x)); }
__device__ __forceinline__ unsigned vld(const unsigned* p) {
    return *(const volatile unsigned*)p;
}

// ------------------------------------------------------------- pack
__global__ void pack_kernel(const float* __restrict__ Wf, const float* __restrict__ Wi,
                            const float* __restrict__ Wc, const float* __restrict__ Wo,
                            const float* __restrict__ bf, const float* __restrict__ bi,
                            const float* __restrict__ bc, const float* __restrict__ bo) {
    const int stride = gridDim.x * blockDim.x;
    const int tid0 = blockIdx.x * blockDim.x + threadIdx.x;
    // Wx packed: [jt][k (512)][c (256)]
    const int NX = NJT * EE * 256;
    for (int idx = tid0; idx < NX; idx += stride) {
        int jt = idx >> 17, r = idx & 131071;
        int kl = r >> 8, c = r & 255;
        int j = jt * 64 + (c >> 2), g = c & 3;
        const float* W = (g == 0) ? Wf : (g == 1) ? Wi : (g == 2) ? Wc : Wo;
        g_Wxp[idx] = W[(size_t)j * DD + kl];
    }
    // Wh packed: [kt*16+jt][k (128)][c (256)]
    const int NH = NKT * NJT * KSL * 256;
    for (int idx = tid0; idx < NH; idx += stride) {
        int cta = idx >> 15, r = idx & 32767;
        int kt = cta >> 4, jt = cta & 15;
        int kl = r >> 8, c = r & 255;
        int j = jt * 64 + (c >> 2), g = c & 3;
        const float* W = (g == 0) ? Wf : (g == 1) ? Wi : (g == 2) ? Wc : Wo;
        g_Whp[idx] = W[(size_t)j * DD + EE + kt * KSL + kl];
    }
    for (int x = tid0; x < GC; x += stride) {
        int j = x >> 2, g = x & 3;  // global col = j*4+g with j = (x>>2)
        // x = jt*256 + c, c = jl*4+g  ->  j = jt*64 + jl = x>>2 ? check:
        // x>>2 = jt*64 + jl  (since c>>2 = jl). Yes.
        const float* b = (g == 0) ? bf : (g == 1) ? bi : (g == 2) ? bc : bo;
        g_biasp[x] = b[j];
    }
    for (int i = tid0; i < BB * HH; i += stride) g_h[0][i] = 0.0f;
    for (int i = tid0; i < NBLK; i += stride) g_flags[i] = 0u;
    for (int i = tid0; i < NJT * NKT; i += stride) ((unsigned*)g_jflags)[i] = 0u;
    if (tid0 == 0) g_rel = 0u;
}

// ------------------------------------------------------------- inner GEMM tile
// sW: [KS][256] weight tile; sH: this warp's 8 rows, pitch 128.
// Thread (warp=rowgroup rg, lane=colgroup cg) accumulates 8 rows x
// cols {4cg..4cg+3} (accA) and {128+4cg..+3} (accB) as f32x2 pairs.
__device__ __forceinline__ void mm_slice(const float* __restrict__ sW,
                                         const float* __restrict__ sH,
                                         int cg, ulonglong2 accA[8], ulonglong2 accB[8]) {
    for (int kb = 0; kb < KSL; kb += 4) {
        float4 hq[8];
        #pragma unroll
        for (int r = 0; r < 8; r++) hq[r] = *(const float4*)&sH[r * KSL + kb];
        #pragma unroll
        for (int u = 0; u < 4; u++) {
            ulonglong2 w0 = *(const ulonglong2*)&sW[(kb + u) * 256 + cg * 4];
            ulonglong2 w1 = *(const ulonglong2*)&sW[(kb + u) * 256 + 128 + cg * 4];
            #pragma unroll
            for (int r = 0; r < 8; r++) {
                float h = (u == 0) ? hq[r].x : (u == 1) ? hq[r].y : (u == 2) ? hq[r].z : hq[r].w;
                ull hh = pack2(h, h);
                fma2(accA[r].x, hh, w0.x); fma2(accA[r].y, hh, w0.y);
                fma2(accB[r].x, hh, w1.x); fma2(accB[r].y, hh, w1.y);
            }
        }
    }
}

// ------------------------------------------------------------- phase 1
__global__ void __launch_bounds__(NTHREADS) gemm_x_kernel(const float* __restrict__ input) {
    extern __shared__ float smem[];
    float* sW = smem;            // [128][256]
    float* sA = smem + 32768;    // [64][128]
    const int t = blockIdx.x, jt = blockIdx.y;
    const int tid = threadIdx.x;
    const int rg = tid >> 5, cg = tid & 31;
    ulonglong2 accA[8], accB[8];
    #pragma unroll
    for (int r = 0; r < 8; r++) { accA[r].x = accA[r].y = 0ull; accB[r].x = accB[r].y = 0ull; }

    for (int kc = 0; kc < EE; kc += KSL) {
        __syncthreads();
        #pragma unroll
        for (int q = 0; q < 8; q++) {       // A: 2048 float4
            int p = tid + q * 256, row = p >> 5, kq = p & 31;
            *(float4*)&sA[row * KSL + kq * 4] =
                *(const float4*)&input[((size_t)row * TT + t) * EE + kc + kq * 4];
        }
        const float4* wsrc = (const float4*)&g_Wxp[((size_t)jt * EE + kc) * 256];
        #pragma unroll
        for (int q = 0; q < 32; q++)        // W: 8192 float4
            ((float4*)sW)[tid + q * 256] = wsrc[tid + q * 256];
        __syncthreads();
        mm_slice(sW, &sA[rg * 8 * KSL], cg, accA, accB);
    }

    ulonglong2 bA = *(const ulonglong2*)&g_biasp[jt * 256 + 4 * cg];
    ulonglong2 bB = *(const ulonglong2*)&g_biasp[jt * 256 + 128 + 4 * cg];
    #pragma unroll
    for (int r = 0; r < 8; r++) {
        int row = rg * 8 + r;
        ulonglong2 oa = accA[r]; add2(oa.x, bA.x); add2(oa.y, bA.y);
        ulonglong2 ob = accB[r]; add2(ob.x, bB.x); add2(ob.y, bB.y);
        float* dst = &g_pre[((size_t)t * BB + row) * GC + jt * 256 + 4 * cg];
        *(ulonglong2*)dst = oa;
        *(ulonglong2*)(dst + 128) = ob;
    }
}

// ------------------------------------------------------------- phase 2
__global__ void __launch_bounds__(NTHREADS) lstm_kernel() {
    extern __shared__ float smem[];
    float* sW = smem;            // [128][256] persistent weight slice
    float* sH = smem + 32768;    // [64][128] h slice for this step
    const int tid = threadIdx.x;
    const int rg = tid >> 5, cg = tid & 31;
    const int kt = blockIdx.x >> 4, jt = blockIdx.x & 15;
    const bool owner = (kt == 0);

    // persistent weight slice (once)
    {
        const float4* wsrc = (const float4*)&g_Whp[(size_t)blockIdx.x * (KSL * 256)];
        #pragma unroll
        for (int q = 0; q < 32; q++)
            ((float4*)sW)[tid + q * 256] = wsrc[tid + q * 256];
    }
    float cst[8][2];
    #pragma unroll
    for (int r = 0; r < 8; r++) cst[r][0] = cst[r][1] = 0.0f;

    for (int t = 0; t < TT; t++) {
        // ---- wait for h(t) (grid barrier release), t=0 ready from pack
        if (t > 0) {
            if (blockIdx.x == 0) {
                if (tid < 32) {
                    for (;;) {
                        unsigned ok = (vld(&g_flags[tid]) >= (unsigned)t) &
                                      (vld(&g_flags[tid + 32]) >= (unsigned)t) &
                                      (vld(&g_flags[tid + 64]) >= (unsigned)t) &
                                      (vld(&g_flags[tid + 96]) >= (unsigned)t);
                        if (__all_sync(0xffffffffu, ok)) break;
                        __nanosleep(64);
                    }
                }
                __syncthreads();
                if (tid == 0) { __threadfence(); *(volatile unsigned*)&g_rel = (unsigned)t; }
            } else {
                if (tid == 0) {
                    while (vld(&g_rel) < (unsigned)t) __nanosleep(64);
                    __threadfence();
                }
                __syncthreads();
            }
        }

        // ---- stage h slice [64][128]
        const float* hcur = g_h[t & 1];
        #pragma unroll
        for (int q = 0; q < 8; q++) {
            int p = tid + q * 256, row = p >> 5, kq = p & 31;
            *(float4*)&sH[row * KSL + kq * 4] =
                __ldcg((const float4*)&hcur[(size_t)row * HH + kt * KSL + kq * 4]);
        }
        __syncthreads();

        ulonglong2 accA[8], accB[8];
        #pragma unroll
        for (int r = 0; r < 8; r++) { accA[r].x = accA[r].y = 0ull; accB[r].x = accB[r].y = 0ull; }
        mm_slice(sW, &sH[rg * 8 * KSL], cg, accA, accB);
        __syncthreads();   // sH reads done before next step's overwrite

        if (!owner) {
            // ---- publish partial sums for this K-slice
            #pragma unroll
            for (int r = 0; r < 8; r++) {
                int row = rg * 8 + r;
                float* dst = &g_part[((size_t)kt * BB + row) * GC + jt * 256 + 4 * cg];
                *(ulonglong2*)dst = accA[r];
                *(ulonglong2*)(dst + 128) = accB[r];
            }
            __threadfence();
            __syncthreads();
            if (tid == 0) *(volatile unsigned*)&g_jflags[jt][kt] = (unsigned)(t + 1);
        } else {
            // ---- wait for the 7 sibling partials
            if (tid == 0) {
                #pragma unroll
                for (int k2 = 1; k2 < NKT; k2++)
                    while (vld(&g_jflags[jt][k2]) < (unsigned)(t + 1)) __nanosleep(32);
                __threadfence();
            }
            __syncthreads();
            // ---- reduce partials + pre, gates, update c/h
            float* hnxt = g_h[(t + 1) & 1];
            #pragma unroll
            for (int r = 0; r < 8; r++) {
                int row = rg * 8 + r;
                ulonglong2 aA = accA[r], aB = accB[r];
                #pragma unroll
                for (int k2 = 1; k2 < NKT; k2++) {
                    const float* src = &g_part[((size_t)k2 * BB + row) * GC + jt * 256 + 4 * cg];
                    ulonglong2 pA = __ldcg((const ulonglong2*)src);
                    ulonglong2 pB = __ldcg((const ulonglong2*)(src + 128));
                    add2(aA.x, pA.x); add2(aA.y, pA.y);
                    add2(aB.x, pB.x); add2(aB.y, pB.y);
                }
                const float* psrc = &g_pre[((size_t)t * BB + row) * GC + jt * 256 + 4 * cg];
                ulonglong2 qA = *(const ulonglong2*)psrc;
                ulonglong2 qB = *(const ulonglong2*)(psrc + 128);
                add2(aA.x, qA.x); add2(aA.y, qA.y);
                add2(aB.x, qB.x); add2(aB.y, qB.y);

                float2 fiA = unpack2(aA.x), coA = unpack2(aA.y);
                float fA = sigf(fiA.x), iA = sigf(fiA.y);
                float gA = tanhf(coA.x), oA = sigf(coA.y);
                cst[r][0] = fA * cst[r][0] + iA * gA;
                hnxt[(size_t)row * HH + jt * 64 + cg] = oA * tanhf(cst[r][0]);

                float2 fiB = unpack2(aB.x), coB = unpack2(aB.y);
                float fB = sigf(fiB.x), iB = sigf(fiB.y);
                float gB = tanhf(coB.x), oB = sigf(coB.y);
                cst[r][1] = fB * cst[r][1] + iB * gB;
                hnxt[(size_t)row * HH + jt * 64 + 32 + cg] = oB * tanhf(cst[r][1]);
            }
            __threadfence();
            __syncthreads();
        }
        // ---- arrive at grid barrier (release happens at next step's wait)
        if (tid == 0) *(volatile unsigned*)&g_flags[blockIdx.x] = (unsigned)(t + 1);
    }
}

// ------------------------------------------------------------- phase 3
__global__ void __launch_bounds__(256) fc_kernel(const float* __restrict__ Wfc,
                                                 const float* __restrict__ bfc,
                                                 float* __restrict__ out) {
    const int b = blockIdx.x;
    const float* h = g_h[0];   // t=511 writes buffer (511+1)&1 = 0
    float p[NCLS];
    #pragma unroll
    for (int c = 0; c < NCLS; c++) p[c] = 0.0f;
    for (int jj = threadIdx.x; jj < HH; jj += 256) {
        float hv = h[(size_t)b * HH + jj];
        #pragma unroll
        for (int c = 0; c < NCLS; c++) p[c] += hv * Wfc[(size_t)c * HH + jj];
    }
    __shared__ float sred[8][NCLS];
    int lane = threadIdx.x & 31, wid = threadIdx.x >> 5;
    #pragma unroll
    for (int c = 0; c < NCLS; c++) {
        #pragma unroll
        for (int off = 16; off; off >>= 1)
            p[c] += __shfl_down_sync(0xffffffffu, p[c], off);
    }
    if (lane == 0) {
        #pragma unroll
        for (int c = 0; c < NCLS; c++) sred[wid][c] = p[c];
    }
    __syncthreads();
    if (threadIdx.x < NCLS) {
        float s = 0.0f;
        #pragma unroll
        for (int w = 0; w < 8; w++) s += sred[w][threadIdx.x];
        out[(size_t)b * NCLS + threadIdx.x] = s + bfc[threadIdx.x];
    }
}

// ------------------------------------------------------------- launch
extern "C" void kernel_launch(void* const* d_in, const int* in_sizes, int n_in,
                              void* d_out, int out_size) {
    const float* input = (const float*)d_in[0];
    const float* Wf = (const float*)d_in[1];
    const float* bf = (const float*)d_in[2];
    const float* Wi = (const float*)d_in[3];
    const float* bi = (const float*)d_in[4];
    const float* Wc = (const float*)d_in[5];
    const float* bc = (const float*)d_in[6];
    const float* Wo = (const float*)d_in[7];
    const float* bo = (const float*)d_in[8];
    const float* Wfc = (const float*)d_in[9];
    const float* bfc = (const float*)d_in[10];
    float* out = (float*)d_out;

    static bool attr_done = false;
    if (!attr_done) {
        cudaFuncSetAttribute(gemm_x_kernel, cudaFuncAttributeMaxDynamicSharedMemorySize, SMEM_BYTES);
        cudaFuncSetAttribute(lstm_kernel, cudaFuncAttributeMaxDynamicSharedMemorySize, SMEM_BYTES);
        attr_done = true;
    }

    pack_kernel<<<2048, 256>>>(Wf, Wi, Wc, Wo, bf, bi, bc, bo);
    dim3 g1(TT, NJT);   // 512 x 16 CTAs
    gemm_x_kernel<<<g1, NTHREADS, SMEM_BYTES>>>(input);
    lstm_kernel<<<NBLK, NTHREADS, SMEM_BYTES>>>();
    fc_kernel<<<BB, 256>>>(Wfc, bfc, out);
}

// round 11
// speedup vs baseline: 1.4455x; 1.4455x over previous
#include <cuda_runtime.h>
#include <cuda_bf16.h>
#include <math.h>
#include <stdint.h>

// LSTM B=64,T=512,E=512,H=1024 -> FC10.
// mma.sync m16n8k16 bf16 hi/lo split (base PTX: works on target sm_103).
#define BB 64
#define TT 512
#define EE 512
#define HH 1024
#define DD 1536
#define NCLS 10
#define NJT 32         // j-tiles of 128 gate rows (r = 4*jl + gate)
#define NKT 4          // phase2 K slices
#define KPT 256        // K per slice
#define PITCH 144      // smem row pitch bytes (64 bf16 + 16B pad) - LDSM conflict-free
// phase2 smem: per buffer WH 18432 | WL 18432 | HH 9216 | HL 9216 = 55296
#define P2BUF 55296
#define P2SD  110592   // sD: [128][66] f32 = 33792
// phase1 smem: per buffer WH 18432 | WL 18432 | XH 18432 | XL 18432 = 73728
#define P1BUF 73728
#define SMEMSZ 147456

static __device__ __nv_bfloat16 g_WhH[(size_t)NJT * 128 * 1024];
static __device__ __nv_bfloat16 g_WhL[(size_t)NJT * 128 * 1024];
static __device__ __nv_bfloat16 g_WxH[(size_t)NJT * 128 * 512];
static __device__ __nv_bfloat16 g_WxL[(size_t)NJT * 128 * 512];
static __device__ __nv_bfloat16 g_xH[(size_t)TT * BB * 512];   // [t][b][k]
static __device__ __nv_bfloat16 g_xL[(size_t)TT * BB * 512];
static __device__ __nv_bfloat16 g_hH[2][BB * HH];              // [b][u]
static __device__ __nv_bfloat16 g_hL[2][BB * HH];
static __device__ float g_pre[(size_t)TT * NJT * 128 * 64];    // [t][jt][r][b] 512MB
static __device__ float g_part[3][NJT][128 * 64];
static __device__ float g_biasp[NJT * 128];
static __device__ float g_hf[BB * HH];
static __device__ unsigned g_flags[NJT];
static __device__ unsigned g_jflags[NJT][NKT];
static __device__ unsigned g_rel;

// ---------------------------------------------------------------- helpers
__device__ __forceinline__ uint32_t smem_u32(const void* p) {
    uint32_t a;
    asm("{ .reg .u64 t; cvta.to.shared.u64 t, %1; cvt.u32.u64 %0, t; }" : "=r"(a) : "l"(p));
    return a;
}
__device__ __forceinline__ void cpa16(uint32_t dst, const void* src) {
    asm volatile("cp.async.cg.shared.global [%0], [%1], 16;" :: "r"(dst), "l"(src));
}
__device__ __forceinline__ void cp_commit() { asm volatile("cp.async.commit_group;" ::: "memory"); }
__device__ __forceinline__ void cp_wait0() { asm volatile("cp.async.wait_group 0;" ::: "memory"); }
__device__ __forceinline__ void cp_wait1() { asm volatile("cp.async.wait_group 1;" ::: "memory"); }
__device__ __forceinline__ void ldsm4(uint32_t r[4], uint32_t a) {
    asm volatile("ldmatrix.sync.aligned.m8n8.x4.shared.b16 {%0,%1,%2,%3}, [%4];"
                 : "=r"(r[0]), "=r"(r[1]), "=r"(r[2]), "=r"(r[3]) : "r"(a));
}
__device__ __forceinline__ void mma_bf16(float d[4], const uint32_t a[4], uint32_t b0, uint32_t b1) {
    asm volatile("mma.sync.aligned.m16n8k16.row.col.f32.bf16.bf16.f32 "
                 "{%0,%1,%2,%3}, {%4,%5,%6,%7}, {%8,%9}, {%0,%1,%2,%3};"
                 : "+f"(d[0]), "+f"(d[1]), "+f"(d[2]), "+f"(d[3])
                 : "r"(a[0]), "r"(a[1]), "r"(a[2]), "r"(a[3]), "r"(b0), "r"(b1));
}
__device__ __forceinline__ float sigx(float x) {
    x = fminf(fmaxf(x, -30.f), 30.f);
    return __fdividef(1.f, 1.f + __expf(-x));
}
__device__ __forceinline__ float tanhx(float x) {
    x = fminf(fmaxf(x, -15.f), 15.f);
    float e = __expf(2.f * x);
    return __fdividef(e - 1.f, e + 1.f);
}
__device__ __forceinline__ unsigned vld(const unsigned* p) { return *(const volatile unsigned*)p; }
__device__ __forceinline__ void split_bf16(float w, __nv_bfloat16& hi, __nv_bfloat16& lo) {
    hi = __float2bfloat16(w);
    lo = __float2bfloat16(w - __bfloat162float(hi));
}

// ---------------------------------------------------------------- pack
__global__ void pack_kernel(const float* __restrict__ input,
                            const float* __restrict__ Wf, const float* __restrict__ Wi,
                            const float* __restrict__ Wc, const float* __restrict__ Wo,
                            const float* __restrict__ bf, const float* __restrict__ bi,
                            const float* __restrict__ bc, const float* __restrict__ bo) {
    const int stride = gridDim.x * blockDim.x;
    const int t0 = blockIdx.x * blockDim.x + threadIdx.x;
    for (int idx = t0; idx < NJT * 128 * 1024; idx += stride) {   // Wh
        int jt = idx >> 17, r = (idx >> 10) & 127, k = idx & 1023;
        int j = jt * 32 + (r >> 2), g = r & 3;
        const float* W = (g == 0) ? Wf : (g == 1) ? Wi : (g == 2) ? Wc : Wo;
        split_bf16(W[(size_t)j * DD + EE + k], g_WhH[idx], g_WhL[idx]);
    }
    for (int idx = t0; idx < NJT * 128 * 512; idx += stride) {    // Wx
        int jt = idx >> 16, r = (idx >> 9) & 127, k = idx & 511;
        int j = jt * 32 + (r >> 2), g = r & 3;
        const float* W = (g == 0) ? Wf : (g == 1) ? Wi : (g == 2) ? Wc : Wo;
        split_bf16(W[(size_t)j * DD + k], g_WxH[idx], g_WxL[idx]);
    }
    for (int idx = t0; idx < TT * BB * 512; idx += stride) {      // x
        int t = idx >> 15, b = (idx >> 9) & 63, k = idx & 511;
        split_bf16(input[((size_t)b * TT + t) * EE + k], g_xH[idx], g_xL[idx]);
    }
    for (int idx = t0; idx < NJT * 128; idx += stride) {
        int jt = idx >> 7, r = idx & 127, g = r & 3;
        const float* bp = (g == 0) ? bf : (g == 1) ? bi : (g == 2) ? bc : bo;
        g_biasp[idx] = bp[jt * 32 + (r >> 2)];
    }
    __nv_bfloat16 z = __float2bfloat16(0.f);
    for (int i = t0; i < BB * HH; i += stride) { g_hH[0][i] = z; g_hL[0][i] = z; }
    for (int i = t0; i < NJT; i += stride) g_flags[i] = 0u;
    for (int i = t0; i < NJT * NKT; i += stride) ((unsigned*)g_jflags)[i] = 0u;
    if (t0 == 0) g_rel = 0u;
}

// ---- stage copies (k-stage of 64): 128-row or 64-row tile, kstride elems
__device__ __forceinline__ void cp_w128(uint32_t dst, const __nv_bfloat16* src, int ks, int tid) {
    #pragma unroll
    for (int q = 0; q < 4; q++) {
        int idx = tid + q * 256, r = idx >> 3, c = idx & 7;
        cpa16(dst + r * PITCH + c * 16, src + (size_t)r * ks + c * 8);
    }
}
__device__ __forceinline__ void cp_h64(uint32_t dst, const __nv_bfloat16* src, int ks, int tid) {
    #pragma unroll
    for (int q = 0; q < 2; q++) {
        int idx = tid + q * 256, r = idx >> 3, c = idx & 7;
        cpa16(dst + r * PITCH + c * 16, src + (size_t)r * ks + c * 8);
    }
}

// ---- one 64-k stage of MMAs. Warp tile 32(M) x NB*8(N). dacc[2*NB][4].
template <int NB>
__device__ __forceinline__ void mma_stage(uint32_t wH, uint32_t wL, uint32_t xH, uint32_t xL,
                                          int r0, int n0, int lane, float (*dacc)[4]) {
    const int arow = lane & 15, akk = (lane >> 4) * 8;
    const int bn = (lane & 7) + ((lane & 16) >> 1), bkk = ((lane >> 3) & 1) * 8;
    #pragma unroll
    for (int kk = 0; kk < 64; kk += 16) {
        uint32_t AH0[4], AH1[4], AL0[4], AL1[4];
        uint32_t ao = (uint32_t)((r0 + arow) * PITCH + (kk + akk) * 2);
        ldsm4(AH0, wH + ao); ldsm4(AH1, wH + ao + 16 * PITCH);
        ldsm4(AL0, wL + ao); ldsm4(AL1, wL + ao + 16 * PITCH);
        #pragma unroll
        for (int g = 0; g < NB / 2; g++) {
            uint32_t BH[4], BL[4];
            uint32_t bo = (uint32_t)((n0 + g * 16 + bn) * PITCH + (kk + bkk) * 2);
            ldsm4(BH, xH + bo); ldsm4(BL, xL + bo);
            float* d00 = dacc[2 * g];      float* d01 = dacc[2 * g + 1];
            float* d10 = dacc[NB + 2 * g]; float* d11 = dacc[NB + 2 * g + 1];
            mma_bf16(d00, AH0, BH[0], BH[1]); mma_bf16(d01, AH0, BH[2], BH[3]);
            mma_bf16(d10, AH1, BH[0], BH[1]); mma_bf16(d11, AH1, BH[2], BH[3]);
            mma_bf16(d00, AH0, BL[0], BL[1]); mma_bf16(d01, AH0, BL[2], BL[3]);
            mma_bf16(d10, AH1, BL[0], BL[1]); mma_bf16(d11, AH1, BL[2], BL[3]);
            mma_bf16(d00, AL0, BH[0], BH[1]); mma_bf16(d01, AL0, BH[2], BH[3]);
            mma_bf16(d10, AL1, BH[0], BH[1]); mma_bf16(d11, AL1, BH[2], BH[3]);
        }
    }
}

// ---------------------------------------------------------------- phase 1
// pre[t][jt][r][b] = x @ Wx^T + bias.  CTA = (t-pair, jt), N=128 (2 timesteps).
__global__ void __launch_bounds__(256) gemm_x_kernel() {
    extern __shared__ unsigned char sm[];
    uint32_t smb = smem_u32(sm);
    const int tid = threadIdx.x, lane = tid & 31, w = tid >> 5;
    const int wm = w & 3, wn = w >> 2;           // warp tile: rows wm*32, cols wn*64
    const int r0 = wm * 32, n0 = wn * 64;
    const int ct = blockIdx.x, jt = blockIdx.y;
    const __nv_bfloat16* WH = g_WxH + (size_t)jt * 128 * 512;
    const __nv_bfloat16* WL = g_WxL + (size_t)jt * 128 * 512;
    const __nv_bfloat16* XH = g_xH + (size_t)(ct * 2) * 64 * 512;   // 128 rows = 2 t
    const __nv_bfloat16* XL = g_xL + (size_t)(ct * 2) * 64 * 512;

    float dacc[16][4];
    #pragma unroll
    for (int i = 0; i < 16; i++)
        #pragma unroll
        for (int e = 0; e < 4; e++) dacc[i][e] = 0.f;

    cp_w128(smb, WH, 512, tid); cp_w128(smb + 18432, WL, 512, tid);
    cp_w128(smb + 36864, XH, 512, tid); cp_w128(smb + 55296, XL, 512, tid);
    cp_commit();
    for (int s = 0; s < 8; s++) {
        if (s < 7) {
            uint32_t nb_ = smb + ((s + 1) & 1) * P1BUF;
            cp_w128(nb_, WH + (s + 1) * 64, 512, tid);
            cp_w128(nb_ + 18432, WL + (s + 1) * 64, 512, tid);
            cp_w128(nb_ + 36864, XH + (s + 1) * 64, 512, tid);
            cp_w128(nb_ + 55296, XL + (s + 1) * 64, 512, tid);
            cp_commit();
            cp_wait1();
        } else cp_wait0();
        __syncthreads();
        uint32_t bb = smb + (s & 1) * P1BUF;
        mma_stage<8>(bb, bb + 18432, bb + 36864, bb + 55296, r0, n0, lane, dacc);
        __syncthreads();
    }
    // epilogue: warp's n block = timestep ct*2 + wn (cols 0..63 local)
    const int tg = ct * 2 + wn;
    float* dst = g_pre + ((size_t)tg * NJT + jt) * 8192;
    #pragma unroll
    for (int mt = 0; mt < 2; mt++) {
        int row = r0 + mt * 16 + (lane >> 2);
        float b0 = g_biasp[jt * 128 + row], b1 = g_biasp[jt * 128 + row + 8];
        #pragma unroll
        for (int nb = 0; nb < 8; nb++) {
            int n = nb * 8 + (lane & 3) * 2;
            float* d = dacc[mt * 8 + nb];
            *(float2*)&dst[row * 64 + n] = make_float2(d[0] + b0, d[1] + b0);
            *(float2*)&dst[(row + 8) * 64 + n] = make_float2(d[2] + b1, d[3] + b1);
        }
    }
}

// ---------------------------------------------------------------- phase 2
// persistent: CTA = jt*4 + kt.  kt=0 owns c-state + gates; kt=1..3 publish partials.
__global__ void __launch_bounds__(256) lstm_kernel() {
    extern __shared__ unsigned char sm[];
    uint32_t smb = smem_u32(sm);
    float* sD = (float*)(sm + P2SD);   // [128][66]
    const int tid = threadIdx.x, lane = tid & 31, w = tid >> 5;
    const int wm = w & 3, wn = w >> 2;
    const int r0 = wm * 32, n0 = wn * 32;
    const int kt = blockIdx.x & 3, jt = blockIdx.x >> 2;
    const bool owner = (kt == 0);
    const int jl = tid >> 3, bg = tid & 7;
    const __nv_bfloat16* WH = g_WhH + (size_t)jt * 128 * 1024 + kt * KPT;
    const __nv_bfloat16* WL = g_WhL + (size_t)jt * 128 * 1024 + kt * KPT;
    float cst[8];
    #pragma unroll
    for (int i = 0; i < 8; i++) cst[i] = 0.f;

    for (int t = 0; t < TT; t++) {
        if (t > 0) {   // grid barrier release: h(t) published by all owners
            if (blockIdx.x == 0) {
                if (tid < 32)
                    while (!__all_sync(0xffffffffu, vld(&g_flags[tid]) >= (unsigned)t))
                        __nanosleep(32);
                __syncthreads();
                if (tid == 0) { __threadfence(); *(volatile unsigned*)&g_rel = (unsigned)t; }
            } else {
                if (tid == 0) {
                    while (vld(&g_rel) < (unsigned)t) __nanosleep(32);
                    __threadfence();
                }
                __syncthreads();
            }
        }
        const __nv_bfloat16* hH = g_hH[t & 1] + kt * KPT;
        const __nv_bfloat16* hL = g_hL[t & 1] + kt * KPT;

        float dacc[8][4];
        #pragma unroll
        for (int i = 0; i < 8; i++)
            #pragma unroll
            for (int e = 0; e < 4; e++) dacc[i][e] = 0.f;

        cp_w128(smb, WH, 1024, tid); cp_w128(smb + 18432, WL, 1024, tid);
        cp_h64(smb + 36864, hH, 1024, tid); cp_h64(smb + 46080, hL, 1024, tid);
        cp_commit();
        for (int s = 0; s < 4; s++) {
            if (s < 3) {
                uint32_t nb_ = smb + ((s + 1) & 1) * P2BUF;
                cp_w128(nb_, WH + (s + 1) * 64, 1024, tid);
                cp_w128(nb_ + 18432, WL + (s + 1) * 64, 1024, tid);
                cp_h64(nb_ + 36864, hH + (s + 1) * 64, 1024, tid);
                cp_h64(nb_ + 46080, hL + (s + 1) * 64, 1024, tid);
                cp_commit();
                cp_wait1();
            } else cp_wait0();
            __syncthreads();
            uint32_t bb = smb + (s & 1) * P2BUF;
            mma_stage<4>(bb, bb + 18432, bb + 36864, bb + 46080, r0, n0, lane, dacc);
            __syncthreads();
        }

        if (!owner) {
            float* pp = g_part[kt - 1][jt];
            #pragma unroll
            for (int mt = 0; mt < 2; mt++) {
                int row = r0 + mt * 16 + (lane >> 2);
                #pragma unroll
                for (int nb = 0; nb < 4; nb++) {
                    int n = n0 + nb * 8 + (lane & 3) * 2;
                    float* d = dacc[mt * 4 + nb];
                    *(float2*)&pp[row * 64 + n] = make_float2(d[0], d[1]);
                    *(float2*)&pp[(row + 8) * 64 + n] = make_float2(d[2], d[3]);
                }
            }
            __threadfence();
            __syncthreads();
            if (tid == 0) *(volatile unsigned*)&g_jflags[jt][kt] = (unsigned)(t + 1);
        } else {
            #pragma unroll
            for (int mt = 0; mt < 2; mt++) {
                int row = r0 + mt * 16 + (lane >> 2);
                #pragma unroll
                for (int nb = 0; nb < 4; nb++) {
                    int n = n0 + nb * 8 + (lane & 3) * 2;
                    float* d = dacc[mt * 4 + nb];
                    *(float2*)&sD[row * 66 + n] = make_float2(d[0], d[1]);
                    *(float2*)&sD[(row + 8) * 66 + n] = make_float2(d[2], d[3]);
                }
            }
            if (tid == 0) {
                #pragma unroll
                for (int k2 = 1; k2 < NKT; k2++)
                    while (vld(&g_jflags[jt][k2]) < (unsigned)(t + 1)) __nanosleep(32);
                __threadfence();
            }
            __syncthreads();
            #pragma unroll
            for (int p = 0; p < 3; p++) {
                const float4* src = (const float4*)g_part[p][jt];
                #pragma unroll
                for (int q = 0; q < 8; q++) {
                    int ii = tid + q * 256;          // float4 idx, 2048 total
                    float4 v = __ldcg(&src[ii]);     // bypass stale L1
                    int row = ii >> 4, cc = (ii & 15) * 4;
                    sD[row * 66 + cc] += v.x; sD[row * 66 + cc + 1] += v.y;
                    sD[row * 66 + cc + 2] += v.z; sD[row * 66 + cc + 3] += v.w;
                }
            }
            __syncthreads();
            // gates: thread owns unit u = jt*32+jl, 8 batches (rotated for banks)
            const float* preb = g_pre + ((size_t)t * NJT + jt) * 8192;
            __nv_bfloat16* oH = g_hH[(t + 1) & 1];
            __nv_bfloat16* oL = g_hL[(t + 1) & 1];
            const int u = jt * 32 + jl;
            #pragma unroll
            for (int i = 0; i < 8; i++) {
                int b = bg * 8 + ((i + jl) & 7);
                float a0 = sD[(4 * jl + 0) * 66 + b] + preb[(4 * jl + 0) * 64 + b];
                float a1 = sD[(4 * jl + 1) * 66 + b] + preb[(4 * jl + 1) * 64 + b];
                float a2 = sD[(4 * jl + 2) * 66 + b] + preb[(4 * jl + 2) * 64 + b];
                float a3 = sD[(4 * jl + 3) * 66 + b] + preb[(4 * jl + 3) * 64 + b];
                float fg = sigx(a0), ig = sigx(a1), gg = tanhx(a2), og = sigx(a3);
                cst[i] = fg * cst[i] + ig * gg;
                float hv = og * tanhx(cst[i]);
                split_bf16(hv, oH[b * HH + u], oL[b * HH + u]);
                if (t == TT - 1) g_hf[(size_t)b * HH + u] = hv;
            }
            __threadfence();
            __syncthreads();
            if (tid == 0) *(volatile unsigned*)&g_flags[jt] = (unsigned)(t + 1);
        }
    }
}

// ---------------------------------------------------------------- phase 3
__global__ void __launch_bounds__(256) fc_kernel(const float* __restrict__ Wfc,
                                                 const float* __restrict__ bfc,
                                                 float* __restrict__ out) {
    const int b = blockIdx.x;
    float p[NCLS];
    #pragma unroll
    for (int c = 0; c < NCLS; c++) p[c] = 0.0f;
    for (int jj = threadIdx.x; jj < HH; jj += 256) {
        float hv = g_hf[(size_t)b * HH + jj];
        #pragma unroll
        for (int c = 0; c < NCLS; c++) p[c] += hv * Wfc[(size_t)c * HH + jj];
    }
    __shared__ float sred[8][NCLS];
    int lane = threadIdx.x & 31, wid = threadIdx.x >> 5;
    #pragma unroll
    for (int c = 0; c < NCLS; c++) {
        #pragma unroll
        for (int off = 16; off; off >>= 1)
            p[c] += __shfl_down_sync(0xffffffffu, p[c], off);
    }
    if (lane == 0) {
        #pragma unroll
        for (int c = 0; c < NCLS; c++) sred[wid][c] = p[c];
    }
    __syncthreads();
    if (threadIdx.x < NCLS) {
        float s = 0.0f;
        #pragma unroll
        for (int w2 = 0; w2 < 8; w2++) s += sred[w2][threadIdx.x];
        out[(size_t)b * NCLS + threadIdx.x] = s + bfc[threadIdx.x];
    }
}

// ---------------------------------------------------------------- launch
extern "C" void kernel_launch(void* const* d_in, const int* in_sizes, int n_in,
                              void* d_out, int out_size) {
    const float* input = (const float*)d_in[0];
    const float* Wf = (const float*)d_in[1];
    const float* bf = (const float*)d_in[2];
    const float* Wi = (const float*)d_in[3];
    const float* bi = (const float*)d_in[4];
    const float* Wc = (const float*)d_in[5];
    const float* bc = (const float*)d_in[6];
    const float* Wo = (const float*)d_in[7];
    const float* bo = (const float*)d_in[8];
    const float* Wfc = (const float*)d_in[9];
    const float* bfc = (const float*)d_in[10];
    float* out = (float*)d_out;

    static bool attr_done = false;
    if (!attr_done) {
        cudaFuncSetAttribute(gemm_x_kernel, cudaFuncAttributeMaxDynamicSharedMemorySize, SMEMSZ);
        cudaFuncSetAttribute(lstm_kernel, cudaFuncAttributeMaxDynamicSharedMemorySize, SMEMSZ);
        attr_done = true;
    }
    pack_kernel<<<4096, 256>>>(input, Wf, Wi, Wc, Wo, bf, bi, bc, bo);
    gemm_x_kernel<<<dim3(TT / 2, NJT), 256, SMEMSZ>>>();
    lstm_kernel<<<NJT * NKT, 256, SMEMSZ>>>();
    fc_kernel<<<BB, 256>>>(Wfc, bfc, out);
}